// round 1
// baseline (speedup 1.0000x reference)
#include <cuda_runtime.h>
#include <cuda_bf16.h>
#include <cstdint>

// Problem constants (fixed by the dataset)
#define BROWS   32768
#define MDIM    512
#define HDIM    256
#define TOTROWS (2 * BROWS)   // both branches stacked

// ---------------------------------------------------------------------------
// Scratch (static device allocations — no cudaMalloc allowed)
// ---------------------------------------------------------------------------
__device__ float g_xc[(size_t)BROWS * MDIM];     // corrupted x          (64 MB)
__device__ float g_buf0[(size_t)TOTROWS * HDIM]; // ping activation      (64 MB)
__device__ float g_buf1[(size_t)TOTROWS * HDIM]; // pong activation      (64 MB)

// ---------------------------------------------------------------------------
// Corruption kernel: per-row stable rank-q selection on u, then
// xc[j] = (rank(u_j) < q) ? low[j] + (high[j]-low[j])*r[j] : x[j]
// Stable ranking == argsort(argsort(u)): key = (float_bits(u) << 9) | j
// ---------------------------------------------------------------------------
__global__ void __launch_bounds__(256) corrupt_kernel(
    const float* __restrict__ x, const float* __restrict__ u,
    const float* __restrict__ r, const float* __restrict__ low,
    const float* __restrict__ high, const int* __restrict__ qptr, int qdef,
    float* __restrict__ xc)
{
    __shared__ float us[MDIM];
    __shared__ int   hist[1024];
    __shared__ int   s_bin, s_rank, s_cnt;
    __shared__ unsigned long long cand[48];
    __shared__ unsigned long long s_thresh;

    const int row = blockIdx.x;
    const int tid = threadIdx.x;
    const size_t base = (size_t)row * MDIM;

    int q = qptr ? *qptr : qdef;

    for (int j = tid; j < MDIM; j += 256) us[j] = u[base + j];
    for (int j = tid; j < 1024; j += 256) hist[j] = 0;
    __syncthreads();

    if (q <= 0) {
        if (tid == 0) s_thresh = 0ULL; // nothing masked (keys are >= 0)
    } else if (q >= MDIM) {
        if (tid == 0) s_thresh = ~0ULL; // everything masked
    }

    if (q > 0 && q < MDIM) {
        for (int j = tid; j < MDIM; j += 256) {
            float v = us[j];
            int b = (int)(v * 1024.0f);
            b = b < 0 ? 0 : (b > 1023 ? 1023 : b);
            atomicAdd(&hist[b], 1);
        }
        __syncthreads();

        // warp 0: find bin containing overall rank q
        if (tid < 32) {
            int s = 0;
            const int b0 = tid * 32;
            #pragma unroll
            for (int b = 0; b < 32; b++) s += hist[b0 + b];
            int pre = s;
            #pragma unroll
            for (int o = 1; o < 32; o <<= 1) {
                int n = __shfl_up_sync(0xffffffffu, pre, o);
                if (tid >= o) pre += n;
            }
            int excl = pre - s;
            if (q >= excl && q < excl + s) {
                int c = excl;
                for (int b = b0; b < b0 + 32; b++) {
                    int h = hist[b];
                    if (q < c + h) { s_bin = b; s_rank = q - c; break; }
                    c += h;
                }
            }
            if (tid == 0) s_cnt = 0;
        }
        __syncthreads();

        const int bsel = s_bin;
        for (int j = tid; j < MDIM; j += 256) {
            float v = us[j];
            int b = (int)(v * 1024.0f);
            b = b < 0 ? 0 : (b > 1023 ? 1023 : b);
            if (b == bsel) {
                int idx = atomicAdd(&s_cnt, 1);
                if (idx < 48)
                    cand[idx] = ((unsigned long long)__float_as_uint(v) << 9)
                                | (unsigned)j;
            }
        }
        __syncthreads();

        if (tid == 0) {
            int cnt = s_cnt < 48 ? s_cnt : 48;
            int rk = s_rank;
            unsigned long long th = 0ULL;
            for (int i = 0; i < cnt; i++) {
                int c = 0;
                for (int k2 = 0; k2 < cnt; k2++) c += (cand[k2] < cand[i]);
                if (c == rk) th = cand[i];
            }
            s_thresh = th;
        }
    }
    __syncthreads();

    const unsigned long long th = s_thresh;
    for (int j = tid; j < MDIM; j += 256) {
        float v = us[j];
        unsigned long long key =
            ((unsigned long long)__float_as_uint(v) << 9) | (unsigned)j;
        bool mask = key < th;
        float lo = low[j], hi = high[j];
        float xr = lo + (hi - lo) * r[base + j];
        xc[base + j] = mask ? xr : x[base + j];
    }
}

// ---------------------------------------------------------------------------
// FP32 tiled GEMM: C[TOTROWS, 256] = act[TOTROWS, K] @ W[K,256] + bias (opt ReLU)
// BM=128, BN=128, BK=8, 256 threads, 8x8 per-thread micro-tile, reg prefetch.
// A2 (if non-null) supplies rows >= rowsA (branch-2 input for layer 1).
// ---------------------------------------------------------------------------
#define BM 128
#define BN 128
#define BKG 8
#define TMR 8
#define TNR 8

template <int K, bool RELU>
__global__ void __launch_bounds__(256) gemm_kernel(
    const float* __restrict__ A, const float* __restrict__ A2, int rowsA,
    const float* __restrict__ W, const float* __restrict__ bias,
    float* __restrict__ C)
{
    __shared__ float As[BKG][BM];
    __shared__ float Bs[BKG][BN];

    const int tid  = threadIdx.x;
    const int col0 = blockIdx.x * BN;
    const int row0 = blockIdx.y * BM;

    const float* Abase = A;
    int rb = row0;
    if (A2 != nullptr && row0 >= rowsA) { Abase = A2; rb = row0 - rowsA; }

    const int aRow = tid >> 1;
    const int aK   = (tid & 1) * 4;
    const int bK   = tid >> 5;
    const int bN   = (tid & 31) * 4;

    const float* aPtr = Abase + (size_t)(rb + aRow) * K + aK;
    const float* bPtr = W + (size_t)bK * HDIM + col0 + bN;

    const int tx = tid & 15;
    const int ty = tid >> 4;

    float acc[TMR][TNR];
    #pragma unroll
    for (int i = 0; i < TMR; i++)
        #pragma unroll
        for (int j = 0; j < TNR; j++) acc[i][j] = 0.0f;

    float4 av = *(const float4*)(aPtr);
    float4 bv = *(const float4*)(bPtr);

    for (int k0 = 0; k0 < K; k0 += BKG) {
        As[aK + 0][aRow] = av.x;
        As[aK + 1][aRow] = av.y;
        As[aK + 2][aRow] = av.z;
        As[aK + 3][aRow] = av.w;
        *(float4*)&Bs[bK][bN] = bv;
        __syncthreads();

        if (k0 + BKG < K) { // prefetch next tiles while computing
            av = *(const float4*)(aPtr + k0 + BKG);
            bv = *(const float4*)(bPtr + (size_t)(k0 + BKG) * HDIM);
        }

        #pragma unroll
        for (int kk = 0; kk < BKG; kk++) {
            float4 a0 = *(const float4*)&As[kk][ty * TMR];
            float4 a1 = *(const float4*)&As[kk][ty * TMR + 4];
            float4 b0 = *(const float4*)&Bs[kk][tx * TNR];
            float4 b1 = *(const float4*)&Bs[kk][tx * TNR + 4];
            float af[8] = {a0.x, a0.y, a0.z, a0.w, a1.x, a1.y, a1.z, a1.w};
            float bf[8] = {b0.x, b0.y, b0.z, b0.w, b1.x, b1.y, b1.z, b1.w};
            #pragma unroll
            for (int i = 0; i < TMR; i++)
                #pragma unroll
                for (int j = 0; j < TNR; j++)
                    acc[i][j] = fmaf(af[i], bf[j], acc[i][j]);
        }
        __syncthreads();
    }

    float bb[TNR];
    #pragma unroll
    for (int j = 0; j < TNR; j++) bb[j] = bias[col0 + tx * TNR + j];

    #pragma unroll
    for (int i = 0; i < TMR; i++) {
        const int row = row0 + ty * TMR + i;
        float4 o0, o1;
        float v;
        v = acc[i][0] + bb[0]; o0.x = RELU ? fmaxf(v, 0.f) : v;
        v = acc[i][1] + bb[1]; o0.y = RELU ? fmaxf(v, 0.f) : v;
        v = acc[i][2] + bb[2]; o0.z = RELU ? fmaxf(v, 0.f) : v;
        v = acc[i][3] + bb[3]; o0.w = RELU ? fmaxf(v, 0.f) : v;
        v = acc[i][4] + bb[4]; o1.x = RELU ? fmaxf(v, 0.f) : v;
        v = acc[i][5] + bb[5]; o1.y = RELU ? fmaxf(v, 0.f) : v;
        v = acc[i][6] + bb[6]; o1.z = RELU ? fmaxf(v, 0.f) : v;
        v = acc[i][7] + bb[7]; o1.w = RELU ? fmaxf(v, 0.f) : v;
        float* cp = C + (size_t)row * HDIM + col0 + tx * TNR;
        *(float4*)cp       = o0;
        *(float4*)(cp + 4) = o1;
    }
}

// ---------------------------------------------------------------------------
// Launch
// ---------------------------------------------------------------------------
extern "C" void kernel_launch(void* const* d_in, const int* in_sizes, int n_in,
                              void* d_out, int out_size)
{
    // Robust input identification by element counts (independent of exact order
    // beyond relative order within each size class).
    const float *x = 0, *u = 0, *r = 0, *low = 0, *high = 0, *We0 = 0;
    const int* qptr = 0;
    const float* W65[8];  int nW = 0;
    const float* b256[8]; int nB = 0;

    for (int i = 0; i < n_in; i++) {
        int s = in_sizes[i];
        const float* p = (const float*)d_in[i];
        if (s == BROWS * MDIM) {
            if (!x) x = p; else if (!u) u = p; else if (!r) r = p;
        } else if (s == MDIM) {
            if (!low) low = p; else if (!high) high = p;
        } else if (s == 1) {
            qptr = (const int*)d_in[i];
        } else if (s == MDIM * HDIM) {
            We0 = p;
        } else if (s == HDIM * HDIM) {
            if (nW < 8) W65[nW++] = p;
        } else if (s == HDIM) {
            if (nB < 8) b256[nB++] = p;
        }
    }
    // Weight order: We0 (512x256); then We1,We2,We3,Wh0,Wh1 among the 256x256;
    // biases in order be0..be3, bh0, bh1.
    const float* Wl[6] = {We0, W65[0], W65[1], W65[2], W65[3], W65[4]};
    const float* bl[6] = {b256[0], b256[1], b256[2], b256[3], b256[4], b256[5]};

    float* xc  = 0;  cudaGetSymbolAddress((void**)&xc,  g_xc);
    float* bf0 = 0;  cudaGetSymbolAddress((void**)&bf0, g_buf0);
    float* bf1 = 0;  cudaGetSymbolAddress((void**)&bf1, g_buf1);
    float* out = (float*)d_out;

    // 1) corruption
    corrupt_kernel<<<BROWS, 256>>>(x, u, r, low, high, qptr, 307, xc);

    // 2) 6 layers, both branches stacked (rows 0..B-1 = clean, B..2B-1 = corrupted)
    dim3 grid(HDIM / BN, TOTROWS / BM);   // (2, 512)
    dim3 blk(256);

    // L1: [x ; xc] @ We0 + be0, ReLU       -> bf0
    gemm_kernel<MDIM, true ><<<grid, blk>>>(x,   xc, BROWS, Wl[0], bl[0], bf0);
    // L2: @ We1 + be1, ReLU                 -> bf1
    gemm_kernel<HDIM, true ><<<grid, blk>>>(bf0, (const float*)0, TOTROWS, Wl[1], bl[1], bf1);
    // L3: @ We2 + be2, ReLU                 -> bf0
    gemm_kernel<HDIM, true ><<<grid, blk>>>(bf1, (const float*)0, TOTROWS, Wl[2], bl[2], bf0);
    // L4: @ We3 + be3 (no ReLU)             -> bf1
    gemm_kernel<HDIM, false><<<grid, blk>>>(bf0, (const float*)0, TOTROWS, Wl[3], bl[3], bf1);
    // L5: @ Wh0 + bh0, ReLU                 -> bf0
    gemm_kernel<HDIM, true ><<<grid, blk>>>(bf1, (const float*)0, TOTROWS, Wl[4], bl[4], bf0);
    // L6: @ Wh1 + bh1 (no ReLU)             -> d_out = [emb ; emb_c]
    gemm_kernel<HDIM, false><<<grid, blk>>>(bf0, (const float*)0, TOTROWS, Wl[5], bl[5], out);

    (void)out_size;
}

// round 3
// speedup vs baseline: 1.5173x; 1.5173x over previous
#include <cuda_runtime.h>
#include <cuda_bf16.h>
#include <cstdint>

// Problem constants (fixed by the dataset)
#define BROWS   32768
#define MDIM    512
#define HDIM    256
#define TOTROWS (2 * BROWS)   // both branches stacked

// ---------------------------------------------------------------------------
// Scratch (static device allocations — no cudaMalloc allowed)
// ---------------------------------------------------------------------------
__device__ float g_xc[(size_t)BROWS * MDIM];       // corrupted x          (64 MB)
__device__ float g_buf0[(size_t)TOTROWS * HDIM];   // ping activation      (64 MB)
__device__ float g_buf1[(size_t)TOTROWS * HDIM];   // pong activation      (64 MB)
__device__ float g_Wf0[(size_t)MDIM * HDIM];       // We0 frag-packed tf32
__device__ float g_WfH[5][(size_t)HDIM * HDIM];    // We1..3,Wh0,Wh1 frag-packed

// ---------------------------------------------------------------------------
// Helpers
// ---------------------------------------------------------------------------
__device__ __forceinline__ uint32_t smem_u32(const void* p) {
    uint32_t a;
    asm("{ .reg .u64 t; cvta.to.shared.u64 t, %1; cvt.u32.u64 %0, t; }"
        : "=r"(a) : "l"(p));
    return a;
}
__device__ __forceinline__ uint32_t cvt_tf32(float f) {
    uint32_t o;
    asm("cvt.rna.tf32.f32 %0, %1;" : "=r"(o) : "f"(f));
    return o;
}
__device__ __forceinline__ void mma_tf32(float* d, const uint32_t* a,
                                         const uint32_t* b) {
    asm volatile(
        "mma.sync.aligned.m16n8k8.row.col.f32.tf32.tf32.f32 "
        "{%0,%1,%2,%3}, {%4,%5,%6,%7}, {%8,%9}, {%0,%1,%2,%3};"
        : "+f"(d[0]), "+f"(d[1]), "+f"(d[2]), "+f"(d[3])
        : "r"(a[0]), "r"(a[1]), "r"(a[2]), "r"(a[3]), "r"(b[0]), "r"(b[1]));
}

// ---------------------------------------------------------------------------
// Corruption kernel (validated rel_err = 0.0 in R1)
// ---------------------------------------------------------------------------
__global__ void __launch_bounds__(256) corrupt_kernel(
    const float* __restrict__ x, const float* __restrict__ u,
    const float* __restrict__ r, const float* __restrict__ low,
    const float* __restrict__ high, const int* __restrict__ qptr, int qdef,
    float* __restrict__ xc)
{
    __shared__ float us[MDIM];
    __shared__ int   hist[1024];
    __shared__ int   s_bin, s_rank, s_cnt;
    __shared__ unsigned long long cand[48];
    __shared__ unsigned long long s_thresh;

    const int row = blockIdx.x;
    const int tid = threadIdx.x;
    const size_t base = (size_t)row * MDIM;

    int q = qptr ? *qptr : qdef;

    for (int j = tid; j < MDIM; j += 256) us[j] = u[base + j];
    for (int j = tid; j < 1024; j += 256) hist[j] = 0;
    __syncthreads();

    if (q <= 0) {
        if (tid == 0) s_thresh = 0ULL;
    } else if (q >= MDIM) {
        if (tid == 0) s_thresh = ~0ULL;
    }

    if (q > 0 && q < MDIM) {
        for (int j = tid; j < MDIM; j += 256) {
            float v = us[j];
            int b = (int)(v * 1024.0f);
            b = b < 0 ? 0 : (b > 1023 ? 1023 : b);
            atomicAdd(&hist[b], 1);
        }
        __syncthreads();

        if (tid < 32) {
            int s = 0;
            const int b0 = tid * 32;
            #pragma unroll
            for (int b = 0; b < 32; b++) s += hist[b0 + b];
            int pre = s;
            #pragma unroll
            for (int o = 1; o < 32; o <<= 1) {
                int n = __shfl_up_sync(0xffffffffu, pre, o);
                if (tid >= o) pre += n;
            }
            int excl = pre - s;
            if (q >= excl && q < excl + s) {
                int c = excl;
                for (int b = b0; b < b0 + 32; b++) {
                    int h = hist[b];
                    if (q < c + h) { s_bin = b; s_rank = q - c; break; }
                    c += h;
                }
            }
            if (tid == 0) s_cnt = 0;
        }
        __syncthreads();

        const int bsel = s_bin;
        for (int j = tid; j < MDIM; j += 256) {
            float v = us[j];
            int b = (int)(v * 1024.0f);
            b = b < 0 ? 0 : (b > 1023 ? 1023 : b);
            if (b == bsel) {
                int idx = atomicAdd(&s_cnt, 1);
                if (idx < 48)
                    cand[idx] = ((unsigned long long)__float_as_uint(v) << 9)
                                | (unsigned)j;
            }
        }
        __syncthreads();

        if (tid == 0) {
            int cnt = s_cnt < 48 ? s_cnt : 48;
            int rk = s_rank;
            unsigned long long th = 0ULL;
            for (int i = 0; i < cnt; i++) {
                int c = 0;
                for (int k2 = 0; k2 < cnt; k2++) c += (cand[k2] < cand[i]);
                if (c == rk) th = cand[i];
            }
            s_thresh = th;
        }
    }
    __syncthreads();

    const unsigned long long th = s_thresh;
    for (int j = tid; j < MDIM; j += 256) {
        float v = us[j];
        unsigned long long key =
            ((unsigned long long)__float_as_uint(v) << 9) | (unsigned)j;
        bool mask = key < th;
        float lo = low[j], hi = high[j];
        float xr = lo + (hi - lo) * r[base + j];
        xc[base + j] = mask ? xr : x[base + j];
    }
}

// ---------------------------------------------------------------------------
// Weight pack: W[K,256] row-major -> B-fragment-major tf32
// Layout: [kblk = k/32][nf = n/8][ks = (k%32)/8][lane][reg 2]
//   lane = (n%8)*4 + (k%4), reg = (k%8)/4
// A CTA's per-chunk slice (8 consecutive nf) is contiguous (2048 floats).
// ---------------------------------------------------------------------------
__global__ void __launch_bounds__(256) pack_w_kernel(
    const float* __restrict__ W, float* __restrict__ Wf, int K)
{
    int idx = blockIdx.x * 256 + threadIdx.x;
    if (idx >= K * HDIM) return;
    int k = idx >> 8;          // row of W
    int n = idx & 255;         // col of W
    int kblk = k >> 5;
    int ks   = (k >> 3) & 3;
    int nf   = n >> 3;
    int lane = ((n & 7) << 2) | (k & 3);
    int reg  = (k >> 2) & 1;
    size_t off = ((((size_t)kblk * 32 + nf) * 4 + ks) * 32 + lane) * 2 + reg;
    Wf[off] = __uint_as_float(cvt_tf32(W[idx]));
}

// ---------------------------------------------------------------------------
// mma.sync tf32 GEMM: C[tile 128 x 64 of 256] = A[.,K] @ W + bias (opt ReLU)
// 256 threads = 8 warps (4 m x 2 n), warp tile 32x32, BK=32, double-buffered
// fragment-major smem, register prefetch, 1 sync per chunk.
// ---------------------------------------------------------------------------
#define A_BUF_F 4096   // 128 x 32 floats
#define B_BUF_F 2048   // 64  x 32 floats

template <int K, bool RELU>
__global__ void __launch_bounds__(256, 2) gemm_mma(
    const float* __restrict__ A, const float* __restrict__ A2, int rowsA,
    const float* __restrict__ Wf, const float* __restrict__ bias,
    float* __restrict__ C)
{
    __shared__ float sA[2][A_BUF_F];
    __shared__ float sB[2][B_BUF_F];

    const int tid  = threadIdx.x;
    const int wid  = tid >> 5;
    const int lane = tid & 31;
    const int wm   = wid >> 1;          // 0..3  (m dir, 32 rows each)
    const int wn   = wid & 1;           // 0..1  (n dir, 32 cols each)

    const int row0 = blockIdx.y * 128;
    const int col0 = blockIdx.x * 64;
    const int nf0  = blockIdx.x * 8;

    const float* Ab = A;
    int rb = row0;
    if (A2 != nullptr && row0 >= rowsA) { Ab = A2; rb = row0 - rowsA; }
    const float* Ag = Ab + (size_t)rb * K;
    const float* Bg = Wf + (size_t)nf0 * 256;   // per-kblk: +8192 floats

    const uint32_t sA_u[2] = { smem_u32(&sA[0][0]), smem_u32(&sA[1][0]) };
    const uint32_t sB_u[2] = { smem_u32(&sB[0][0]), smem_u32(&sB[1][0]) };

    // Precomputed A-staging store addresses (4 stores per float4, reg fixed)
    // fi = tid + i*256 ; r = fi>>3 ; cq = fi&7
    // mfrag=r>>4, ks=cq>>1, lane_t=((r&7)<<2)|j, reg=((r>>3)&1)|((cq&1)<<1)
    uint32_t aSt[4];   // base byte offsets (j=0), per i
    #pragma unroll
    for (int i = 0; i < 4; i++) {
        int fi = tid + i * 256;
        int r = fi >> 3, cq = fi & 7;
        int mfrag = r >> 4, ks = cq >> 1;
        int lt = (r & 7) << 2;
        int reg = ((r >> 3) & 1) | ((cq & 1) << 1);
        aSt[i] = (uint32_t)((((mfrag * 4 + ks) * 32 + lt) * 4 + reg) * 4);
    }

    float acc[2][4][4];
    #pragma unroll
    for (int mi = 0; mi < 2; mi++)
        #pragma unroll
        for (int ni = 0; ni < 4; ni++)
            #pragma unroll
            for (int j = 0; j < 4; j++) acc[mi][ni][j] = 0.0f;

    const int NC = K / 32;
    float4 Ar[4], Br[2];

    // ---- prologue: chunk 0 -> regs -> buf0 ; chunk 1 -> regs ----
    #pragma unroll
    for (int i = 0; i < 4; i++) {
        int fi = tid + i * 256;
        Ar[i] = *(const float4*)(Ag + (size_t)(fi >> 3) * K + (fi & 7) * 4);
    }
    #pragma unroll
    for (int i = 0; i < 2; i++) {
        int fi = tid + i * 256;
        Br[i] = *(const float4*)(Bg + fi * 4);
    }
    #pragma unroll
    for (int i = 0; i < 4; i++) {
        const float* af = (const float*)&Ar[i];
        #pragma unroll
        for (int j = 0; j < 4; j++) {
            uint32_t v = cvt_tf32(af[j]);
            asm volatile("st.shared.b32 [%0], %1;"
                         :: "r"(sA_u[0] + aSt[i] + j * 16), "r"(v));
        }
    }
    #pragma unroll
    for (int i = 0; i < 2; i++) {
        int fi = tid + i * 256;
        asm volatile("st.shared.v4.b32 [%0], {%1,%2,%3,%4};"
                     :: "r"(sB_u[0] + fi * 16),
                        "r"(__float_as_uint(Br[i].x)), "r"(__float_as_uint(Br[i].y)),
                        "r"(__float_as_uint(Br[i].z)), "r"(__float_as_uint(Br[i].w)));
    }
    if (NC > 1) {
        #pragma unroll
        for (int i = 0; i < 4; i++) {
            int fi = tid + i * 256;
            Ar[i] = *(const float4*)(Ag + (size_t)(fi >> 3) * K + 32 + (fi & 7) * 4);
        }
        #pragma unroll
        for (int i = 0; i < 2; i++) {
            int fi = tid + i * 256;
            Br[i] = *(const float4*)(Bg + 8192 + fi * 4);
        }
    }
    __syncthreads();

    // ---- main loop ----
    for (int c = 0; c < NC; c++) {
        const int cur = c & 1;
        const int nxt = cur ^ 1;

        if (c + 1 < NC) {   // store prefetched chunk c+1 into the other buffer
            #pragma unroll
            for (int i = 0; i < 4; i++) {
                const float* af = (const float*)&Ar[i];
                #pragma unroll
                for (int j = 0; j < 4; j++) {
                    uint32_t v = cvt_tf32(af[j]);
                    asm volatile("st.shared.b32 [%0], %1;"
                                 :: "r"(sA_u[nxt] + aSt[i] + j * 16), "r"(v));
                }
            }
            #pragma unroll
            for (int i = 0; i < 2; i++) {
                int fi = tid + i * 256;
                asm volatile("st.shared.v4.b32 [%0], {%1,%2,%3,%4};"
                             :: "r"(sB_u[nxt] + fi * 16),
                                "r"(__float_as_uint(Br[i].x)), "r"(__float_as_uint(Br[i].y)),
                                "r"(__float_as_uint(Br[i].z)), "r"(__float_as_uint(Br[i].w)));
            }
        }
        if (c + 2 < NC) {   // start global loads for chunk c+2
            #pragma unroll
            for (int i = 0; i < 4; i++) {
                int fi = tid + i * 256;
                Ar[i] = *(const float4*)(Ag + (size_t)(fi >> 3) * K
                                         + (c + 2) * 32 + (fi & 7) * 4);
            }
            #pragma unroll
            for (int i = 0; i < 2; i++) {
                int fi = tid + i * 256;
                Br[i] = *(const float4*)(Bg + (size_t)(c + 2) * 8192 + fi * 4);
            }
        }

        // compute on buffer `cur`
        #pragma unroll
        for (int ks = 0; ks < 4; ks++) {
            uint32_t a[2][4], b[4][2];
            #pragma unroll
            for (int mi = 0; mi < 2; mi++) {
                uint32_t addr = sA_u[cur]
                    + ((((wm * 2 + mi) * 4 + ks) * 32 + lane) * 16);
                asm volatile("ld.shared.v4.b32 {%0,%1,%2,%3}, [%4];"
                             : "=r"(a[mi][0]), "=r"(a[mi][1]),
                               "=r"(a[mi][2]), "=r"(a[mi][3])
                             : "r"(addr));
            }
            #pragma unroll
            for (int ni = 0; ni < 4; ni++) {
                uint32_t addr = sB_u[cur]
                    + ((((wn * 4 + ni) * 4 + ks) * 32 + lane) * 8);
                asm volatile("ld.shared.v2.b32 {%0,%1}, [%2];"
                             : "=r"(b[ni][0]), "=r"(b[ni][1]) : "r"(addr));
            }
            #pragma unroll
            for (int mi = 0; mi < 2; mi++)
                #pragma unroll
                for (int ni = 0; ni < 4; ni++)
                    mma_tf32(acc[mi][ni], a[mi], b[ni]);
        }
        __syncthreads();
    }

    // ---- epilogue: bias + optional ReLU, float2 stores ----
    #pragma unroll
    for (int mi = 0; mi < 2; mi++) {
        const int m0 = row0 + wm * 32 + mi * 16 + (lane >> 2);
        #pragma unroll
        for (int ni = 0; ni < 4; ni++) {
            const int gcol = col0 + wn * 32 + ni * 8 + (lane & 3) * 2;
            float2 bb = *(const float2*)(bias + gcol);
            float v0 = acc[mi][ni][0] + bb.x;
            float v1 = acc[mi][ni][1] + bb.y;
            float v2 = acc[mi][ni][2] + bb.x;
            float v3 = acc[mi][ni][3] + bb.y;
            if (RELU) {
                v0 = fmaxf(v0, 0.f); v1 = fmaxf(v1, 0.f);
                v2 = fmaxf(v2, 0.f); v3 = fmaxf(v3, 0.f);
            }
            *(float2*)(C + (size_t)m0 * HDIM + gcol)       = make_float2(v0, v1);
            *(float2*)(C + (size_t)(m0 + 8) * HDIM + gcol) = make_float2(v2, v3);
        }
    }
}

// ---------------------------------------------------------------------------
// Launch
// ---------------------------------------------------------------------------
extern "C" void kernel_launch(void* const* d_in, const int* in_sizes, int n_in,
                              void* d_out, int out_size)
{
    const float *x = 0, *u = 0, *r = 0, *low = 0, *high = 0, *We0 = 0;
    const int* qptr = 0;
    const float* W65[8];  int nW = 0;
    const float* b256[8]; int nB = 0;

    for (int i = 0; i < n_in; i++) {
        int s = in_sizes[i];
        const float* p = (const float*)d_in[i];
        if (s == BROWS * MDIM) {
            if (!x) x = p; else if (!u) u = p; else if (!r) r = p;
        } else if (s == MDIM) {
            if (!low) low = p; else if (!high) high = p;
        } else if (s == 1) {
            qptr = (const int*)d_in[i];
        } else if (s == MDIM * HDIM) {
            We0 = p;
        } else if (s == HDIM * HDIM) {
            if (nW < 8) W65[nW++] = p;
        } else if (s == HDIM) {
            if (nB < 8) b256[nB++] = p;
        }
    }
    const float* bl[6] = {b256[0], b256[1], b256[2], b256[3], b256[4], b256[5]};

    float* xc  = 0; cudaGetSymbolAddress((void**)&xc,  g_xc);
    float* bf0 = 0; cudaGetSymbolAddress((void**)&bf0, g_buf0);
    float* bf1 = 0; cudaGetSymbolAddress((void**)&bf1, g_buf1);
    float* wf0 = 0; cudaGetSymbolAddress((void**)&wf0, g_Wf0);
    float* wfH = 0; cudaGetSymbolAddress((void**)&wfH, g_WfH);
    float* out = (float*)d_out;

    // 1) corruption
    corrupt_kernel<<<BROWS, 256>>>(x, u, r, low, high, qptr, 307, xc);

    // 2) weight fragment-packing (tiny)
    pack_w_kernel<<<(MDIM * HDIM) / 256, 256>>>(We0, wf0, MDIM);
    for (int i = 0; i < 5; i++)
        pack_w_kernel<<<(HDIM * HDIM) / 256, 256>>>(
            W65[i], wfH + (size_t)i * HDIM * HDIM, HDIM);

    // 3) 6 layers on mma.sync tensor cores, both branches stacked
    dim3 grid(HDIM / 64, TOTROWS / 128);   // (4, 512)
    dim3 blk(256);

    gemm_mma<MDIM, true ><<<grid, blk>>>(x,   xc, BROWS, wf0, bl[0], bf0);
    gemm_mma<HDIM, true ><<<grid, blk>>>(bf0, (const float*)0, TOTROWS,
                                         wfH + 0 * HDIM * HDIM, bl[1], bf1);
    gemm_mma<HDIM, true ><<<grid, blk>>>(bf1, (const float*)0, TOTROWS,
                                         wfH + 1 * HDIM * HDIM, bl[2], bf0);
    gemm_mma<HDIM, false><<<grid, blk>>>(bf0, (const float*)0, TOTROWS,
                                         wfH + 2 * HDIM * HDIM, bl[3], bf1);
    gemm_mma<HDIM, true ><<<grid, blk>>>(bf1, (const float*)0, TOTROWS,
                                         wfH + 3 * HDIM * HDIM, bl[4], bf0);
    gemm_mma<HDIM, false><<<grid, blk>>>(bf0, (const float*)0, TOTROWS,
                                         wfH + 4 * HDIM * HDIM, bl[5], out);

    (void)out_size;
}

// round 4
// speedup vs baseline: 2.3743x; 1.5648x over previous
#include <cuda_runtime.h>
#include <cuda_bf16.h>
#include <cstdint>

// Problem constants (fixed by the dataset)
#define BROWS   32768
#define MDIM    512
#define HDIM    256
#define TOTROWS (2 * BROWS)   // both branches stacked

// ---------------------------------------------------------------------------
// Scratch (static device allocations — no cudaMalloc allowed)
// ---------------------------------------------------------------------------
__device__ __align__(16) uint32_t g_xp [(size_t)BROWS * MDIM];   // packed split(x)
__device__ __align__(16) uint32_t g_xcp[(size_t)BROWS * MDIM];   // packed split(xc)
__device__ __align__(16) uint32_t g_act0[(size_t)TOTROWS * HDIM];
__device__ __align__(16) uint32_t g_act1[(size_t)TOTROWS * HDIM];
// Weights, fragment-major bf16, hi/lo planes (u32 = 2 bf16)
__device__ __align__(16) uint32_t g_Wf0p[2][(size_t)MDIM * HDIM / 2];
__device__ __align__(16) uint32_t g_WfHp[5][2][(size_t)HDIM * HDIM / 2];

// ---------------------------------------------------------------------------
// Helpers
// ---------------------------------------------------------------------------
__device__ __forceinline__ uint32_t smem_u32(const void* p) {
    uint32_t a;
    asm("{ .reg .u64 t; cvta.to.shared.u64 t, %1; cvt.u32.u64 %0, t; }"
        : "=r"(a) : "l"(p));
    return a;
}
// split fp32 -> (hi bf16 in bits[31:16], lo bf16 in bits[15:0])
__device__ __forceinline__ uint32_t pack_split(float v) {
    __nv_bfloat16 h = __float2bfloat16_rn(v);
    float rem = v - __bfloat162float(h);
    __nv_bfloat16 l = __float2bfloat16_rn(rem);
    return ((uint32_t)__bfloat16_as_ushort(h) << 16) |
           (uint32_t)__bfloat16_as_ushort(l);
}
__device__ __forceinline__ void mma_bf16(float* d, const uint32_t* a,
                                         uint32_t b0, uint32_t b1) {
    asm volatile(
        "mma.sync.aligned.m16n8k16.row.col.f32.bf16.bf16.f32 "
        "{%0,%1,%2,%3}, {%4,%5,%6,%7}, {%8,%9}, {%0,%1,%2,%3};"
        : "+f"(d[0]), "+f"(d[1]), "+f"(d[2]), "+f"(d[3])
        : "r"(a[0]), "r"(a[1]), "r"(a[2]), "r"(a[3]), "r"(b0), "r"(b1));
}
#define CP_ASYNC16(dst, src) \
    asm volatile("cp.async.cg.shared.global [%0], [%1], 16;" :: "r"(dst), "l"(src))
#define CP_COMMIT() asm volatile("cp.async.commit_group;" ::: "memory")
#define CP_WAIT0()  asm volatile("cp.async.wait_group 0;" ::: "memory")

// ---------------------------------------------------------------------------
// Corruption kernel (rank-q logic validated rel_err = 0.0 in R1),
// now emits packed-split x and xc.
// ---------------------------------------------------------------------------
__global__ void __launch_bounds__(256) corrupt_kernel(
    const float* __restrict__ x, const float* __restrict__ u,
    const float* __restrict__ r, const float* __restrict__ low,
    const float* __restrict__ high, const int* __restrict__ qptr, int qdef,
    uint32_t* __restrict__ xp, uint32_t* __restrict__ xcp)
{
    __shared__ float us[MDIM];
    __shared__ int   hist[1024];
    __shared__ int   s_bin, s_rank, s_cnt;
    __shared__ unsigned long long cand[48];
    __shared__ unsigned long long s_thresh;

    const int row = blockIdx.x;
    const int tid = threadIdx.x;
    const size_t base = (size_t)row * MDIM;

    int q = qptr ? *qptr : qdef;

    for (int j = tid; j < MDIM; j += 256) us[j] = u[base + j];
    for (int j = tid; j < 1024; j += 256) hist[j] = 0;
    __syncthreads();

    if (q <= 0) {
        if (tid == 0) s_thresh = 0ULL;
    } else if (q >= MDIM) {
        if (tid == 0) s_thresh = ~0ULL;
    }

    if (q > 0 && q < MDIM) {
        for (int j = tid; j < MDIM; j += 256) {
            float v = us[j];
            int b = (int)(v * 1024.0f);
            b = b < 0 ? 0 : (b > 1023 ? 1023 : b);
            atomicAdd(&hist[b], 1);
        }
        __syncthreads();

        if (tid < 32) {
            int s = 0;
            const int b0 = tid * 32;
            #pragma unroll
            for (int b = 0; b < 32; b++) s += hist[b0 + b];
            int pre = s;
            #pragma unroll
            for (int o = 1; o < 32; o <<= 1) {
                int n = __shfl_up_sync(0xffffffffu, pre, o);
                if (tid >= o) pre += n;
            }
            int excl = pre - s;
            if (q >= excl && q < excl + s) {
                int c = excl;
                for (int b = b0; b < b0 + 32; b++) {
                    int h = hist[b];
                    if (q < c + h) { s_bin = b; s_rank = q - c; break; }
                    c += h;
                }
            }
            if (tid == 0) s_cnt = 0;
        }
        __syncthreads();

        const int bsel = s_bin;
        for (int j = tid; j < MDIM; j += 256) {
            float v = us[j];
            int b = (int)(v * 1024.0f);
            b = b < 0 ? 0 : (b > 1023 ? 1023 : b);
            if (b == bsel) {
                int idx = atomicAdd(&s_cnt, 1);
                if (idx < 48)
                    cand[idx] = ((unsigned long long)__float_as_uint(v) << 9)
                                | (unsigned)j;
            }
        }
        __syncthreads();

        if (tid == 0) {
            int cnt = s_cnt < 48 ? s_cnt : 48;
            int rk = s_rank;
            unsigned long long th = 0ULL;
            for (int i = 0; i < cnt; i++) {
                int c = 0;
                for (int k2 = 0; k2 < cnt; k2++) c += (cand[k2] < cand[i]);
                if (c == rk) th = cand[i];
            }
            s_thresh = th;
        }
    }
    __syncthreads();

    const unsigned long long th = s_thresh;
    for (int j = tid; j < MDIM; j += 256) {
        float v = us[j];
        unsigned long long key =
            ((unsigned long long)__float_as_uint(v) << 9) | (unsigned)j;
        bool mask = key < th;
        float lo = low[j], hi = high[j];
        float xr = lo + (hi - lo) * r[base + j];
        float xv = x[base + j];
        xp [base + j] = pack_split(xv);
        xcp[base + j] = pack_split(mask ? xr : xv);
    }
}

// ---------------------------------------------------------------------------
// Weight pack: W[K,256] row-major -> bf16 B-fragment planes (hi, lo).
// m16n8k16 B frag: b0 = (k%16<8), b1 = (k%16>=8); lane=(n%8)*4+((k%8)/2);
// u32 holds k-pair (even k in low 16 bits).
// u32 index = (((kblk*32 + nf)*2 + kstep)*32 + lane)*2 + reg
// ---------------------------------------------------------------------------
__global__ void __launch_bounds__(256) pack_w_kernel(
    const float* __restrict__ W, uint32_t* __restrict__ WfHi,
    uint32_t* __restrict__ WfLo, int K)
{
    int idx = blockIdx.x * 256 + threadIdx.x;   // over K/2 * 256
    if (idx >= (K / 2) * HDIM) return;
    int k2 = idx >> 8;
    int n  = idx & 255;
    int k  = k2 * 2;
    uint32_t p0 = pack_split(W[(size_t)k * HDIM + n]);
    uint32_t p1 = pack_split(W[(size_t)(k + 1) * HDIM + n]);
    uint32_t hiW = (p0 >> 16) | (p1 & 0xFFFF0000u);          // even k low
    uint32_t loW = (p0 & 0xFFFFu) | ((p1 & 0xFFFFu) << 16);

    int kblk = k >> 5, ks = (k >> 4) & 1, rem = k & 15;
    int reg = rem >> 3, tig = (rem & 7) >> 1;
    int nf = n >> 3, lane = ((n & 7) << 2) | tig;
    size_t i32 = ((((size_t)kblk * 32 + nf) * 2 + ks) * 32 + lane) * 2 + reg;
    WfHi[i32] = hiW;
    WfLo[i32] = loW;
}

// ---------------------------------------------------------------------------
// bf16 split-3 GEMM: C[128x128 tile of 256] = A @ W + bias
// A: packed (hi,lo) u32, row-major. W: frag-major planes.
// 8 warps (4m x 2n), warp tile 32x64, BK=32, double-buffered cp.async.
// ---------------------------------------------------------------------------
#define DSMEM_SZ (2 * 16384 /*A*/ + 2 * 16384 /*B*/ + 512 /*bias*/)

template <int K, bool RELU, bool PACKOUT>
__global__ void __launch_bounds__(256, 2) gemm_bf16x3(
    const uint32_t* __restrict__ A, const uint32_t* __restrict__ A2, int rowsA,
    const uint32_t* __restrict__ WfHi, const uint32_t* __restrict__ WfLo,
    const float* __restrict__ bias, void* __restrict__ Cout)
{
    extern __shared__ __align__(16) char dsm[];
    const int tid  = threadIdx.x;
    const int lane = tid & 31;
    const int wid  = tid >> 5;
    const int wm   = wid >> 1;     // 0..3, 32 rows each
    const int wn   = wid & 1;      // 0..1, 64 cols each

    const int row0 = blockIdx.y * 128;
    const int col0 = blockIdx.x * 128;
    const int nf0  = blockIdx.x * 16;

    const uint32_t base = smem_u32(dsm);
    const uint32_t sA [2] = { base,                 base + 16384 };
    const uint32_t sBh[2] = { base + 32768,         base + 49152 };
    const uint32_t sBl[2] = { base + 32768 + 8192,  base + 49152 + 8192 };
    float* s_bias = (float*)(dsm + 65536);

    const uint32_t* Ab = A;
    int rb = row0;
    if (A2 != nullptr && row0 >= rowsA) { Ab = A2; rb = row0 - rowsA; }
    const uint32_t* Ag = Ab + (size_t)rb * K;

    if (tid < 128) s_bias[tid] = bias[col0 + tid];

    const int NC = K / 32;

    // ---- cp.async staging of chunk c into buffer buf ----
    auto issue = [&](int c, int buf) {
        // A: 128 rows x 32 u32 = 1024 x 16B units, swizzled
        #pragma unroll
        for (int i = 0; i < 4; i++) {
            int unit = tid + i * 256;
            int m = unit >> 3, k4 = unit & 7;
            const uint32_t* src = Ag + (size_t)m * K + c * 32 + k4 * 4;
            uint32_t dst = sA[buf] + m * 128 + ((k4 ^ (m & 7)) << 4);
            CP_ASYNC16(dst, src);
        }
        // B: per plane 512 x 16B units (fragment-major contiguous slice)
        size_t bOff = ((size_t)c * 32 + nf0) * 128;   // u32 index
        #pragma unroll
        for (int i = 0; i < 2; i++) {
            int unit = tid + i * 256;
            CP_ASYNC16(sBh[buf] + unit * 16, WfHi + bOff + unit * 4);
            CP_ASYNC16(sBl[buf] + unit * 16, WfLo + bOff + unit * 4);
        }
    };

    issue(0, 0);
    CP_COMMIT();
    CP_WAIT0();
    __syncthreads();

    float acc[2][8][4];
    #pragma unroll
    for (int mi = 0; mi < 2; mi++)
        #pragma unroll
        for (int ni = 0; ni < 8; ni++)
            #pragma unroll
            for (int j = 0; j < 4; j++) acc[mi][ni][j] = 0.0f;

    const int g8 = lane >> 2;       // row-in-group 0..7
    const int tg = lane & 3;        // k-pair selector

    for (int c = 0; c < NC; c++) {
        const int cur = c & 1;
        if (c + 1 < NC) { issue(c + 1, cur ^ 1); CP_COMMIT(); }

        #pragma unroll
        for (int ks = 0; ks < 2; ks++) {
            uint32_t aHi[2][4], aLo[2][4];
            #pragma unroll
            for (int mi = 0; mi < 2; mi++) {
                const int mg = wm * 32 + mi * 16 + g8;
                const int kA = ks * 16 + tg * 2;
                const int s0 = (kA >> 2) ^ g8;
                const int s1 = ((kA >> 2) + 2) ^ g8;
                const int o  = (kA & 3) * 4;
                uint32_t a00 = sA[cur] + mg * 128 + (s0 << 4) + o;
                uint32_t a01 = sA[cur] + mg * 128 + (s1 << 4) + o;
                uint32_t w0, w1, w2, w3, w4, w5, w6, w7;
                asm volatile("ld.shared.v2.b32 {%0,%1}, [%2];"
                             : "=r"(w0), "=r"(w1) : "r"(a00));
                asm volatile("ld.shared.v2.b32 {%0,%1}, [%2];"
                             : "=r"(w2), "=r"(w3) : "r"(a00 + 1024));
                asm volatile("ld.shared.v2.b32 {%0,%1}, [%2];"
                             : "=r"(w4), "=r"(w5) : "r"(a01));
                asm volatile("ld.shared.v2.b32 {%0,%1}, [%2];"
                             : "=r"(w6), "=r"(w7) : "r"(a01 + 1024));
                aHi[mi][0] = __byte_perm(w0, w1, 0x7632);
                aLo[mi][0] = __byte_perm(w0, w1, 0x5410);
                aHi[mi][1] = __byte_perm(w2, w3, 0x7632);
                aLo[mi][1] = __byte_perm(w2, w3, 0x5410);
                aHi[mi][2] = __byte_perm(w4, w5, 0x7632);
                aLo[mi][2] = __byte_perm(w4, w5, 0x5410);
                aHi[mi][3] = __byte_perm(w6, w7, 0x7632);
                aLo[mi][3] = __byte_perm(w6, w7, 0x5410);
            }
            #pragma unroll
            for (int ni = 0; ni < 8; ni++) {
                const int nfL = wn * 8 + ni;
                const uint32_t boff = (uint32_t)(((nfL * 2 + ks) * 32 + lane) * 8);
                uint32_t bh0, bh1, bl0, bl1;
                asm volatile("ld.shared.v2.b32 {%0,%1}, [%2];"
                             : "=r"(bh0), "=r"(bh1) : "r"(sBh[cur] + boff));
                asm volatile("ld.shared.v2.b32 {%0,%1}, [%2];"
                             : "=r"(bl0), "=r"(bl1) : "r"(sBl[cur] + boff));
                #pragma unroll
                for (int mi = 0; mi < 2; mi++) {
                    mma_bf16(acc[mi][ni], aHi[mi], bh0, bh1);
                    mma_bf16(acc[mi][ni], aHi[mi], bl0, bl1);
                    mma_bf16(acc[mi][ni], aLo[mi], bh0, bh1);
                }
            }
        }
        if (c + 1 < NC) { CP_WAIT0(); __syncthreads(); }
    }

    // ---- epilogue ----
    #pragma unroll
    for (int mi = 0; mi < 2; mi++) {
        const int m = row0 + wm * 32 + mi * 16 + g8;
        #pragma unroll
        for (int ni = 0; ni < 8; ni++) {
            const int nl = wn * 64 + ni * 8 + tg * 2;
            const float b0 = s_bias[nl], b1 = s_bias[nl + 1];
            float v0 = acc[mi][ni][0] + b0;
            float v1 = acc[mi][ni][1] + b1;
            float v2 = acc[mi][ni][2] + b0;
            float v3 = acc[mi][ni][3] + b1;
            if (RELU) {
                v0 = fmaxf(v0, 0.f); v1 = fmaxf(v1, 0.f);
                v2 = fmaxf(v2, 0.f); v3 = fmaxf(v3, 0.f);
            }
            const size_t c0i = (size_t)m * HDIM + col0 + nl;
            const size_t c1i = (size_t)(m + 8) * HDIM + col0 + nl;
            if (PACKOUT) {
                uint32_t* C = (uint32_t*)Cout;
                *(uint2*)(C + c0i) = make_uint2(pack_split(v0), pack_split(v1));
                *(uint2*)(C + c1i) = make_uint2(pack_split(v2), pack_split(v3));
            } else {
                float* C = (float*)Cout;
                *(float2*)(C + c0i) = make_float2(v0, v1);
                *(float2*)(C + c1i) = make_float2(v2, v3);
            }
        }
    }
}

// ---------------------------------------------------------------------------
// Launch
// ---------------------------------------------------------------------------
extern "C" void kernel_launch(void* const* d_in, const int* in_sizes, int n_in,
                              void* d_out, int out_size)
{
    const float *x = 0, *u = 0, *r = 0, *low = 0, *high = 0, *We0 = 0;
    const int* qptr = 0;
    const float* W65[8];  int nW = 0;
    const float* b256[8]; int nB = 0;

    for (int i = 0; i < n_in; i++) {
        int s = in_sizes[i];
        const float* p = (const float*)d_in[i];
        if (s == BROWS * MDIM) {
            if (!x) x = p; else if (!u) u = p; else if (!r) r = p;
        } else if (s == MDIM) {
            if (!low) low = p; else if (!high) high = p;
        } else if (s == 1) {
            qptr = (const int*)d_in[i];
        } else if (s == MDIM * HDIM) {
            We0 = p;
        } else if (s == HDIM * HDIM) {
            if (nW < 8) W65[nW++] = p;
        } else if (s == HDIM) {
            if (nB < 8) b256[nB++] = p;
        }
    }
    const float* bl[6] = {b256[0], b256[1], b256[2], b256[3], b256[4], b256[5]};

    uint32_t* xp  = 0; cudaGetSymbolAddress((void**)&xp,  g_xp);
    uint32_t* xcp = 0; cudaGetSymbolAddress((void**)&xcp, g_xcp);
    uint32_t* a0  = 0; cudaGetSymbolAddress((void**)&a0,  g_act0);
    uint32_t* a1  = 0; cudaGetSymbolAddress((void**)&a1,  g_act1);
    uint32_t* w0p = 0; cudaGetSymbolAddress((void**)&w0p, g_Wf0p);
    uint32_t* wHp = 0; cudaGetSymbolAddress((void**)&wHp, g_WfHp);
    float* out = (float*)d_out;

    const size_t W0PLANE = (size_t)MDIM * HDIM / 2;
    const size_t WHPLANE = (size_t)HDIM * HDIM / 2;
    uint32_t* w0hi = w0p;
    uint32_t* w0lo = w0p + W0PLANE;
    auto whi = [&](int i) { return wHp + (size_t)i * 2 * WHPLANE; };
    auto wlo = [&](int i) { return wHp + (size_t)i * 2 * WHPLANE + WHPLANE; };

    cudaFuncSetAttribute(gemm_bf16x3<MDIM, true,  true >, cudaFuncAttributeMaxDynamicSharedMemorySize, DSMEM_SZ);
    cudaFuncSetAttribute(gemm_bf16x3<HDIM, true,  true >, cudaFuncAttributeMaxDynamicSharedMemorySize, DSMEM_SZ);
    cudaFuncSetAttribute(gemm_bf16x3<HDIM, false, true >, cudaFuncAttributeMaxDynamicSharedMemorySize, DSMEM_SZ);
    cudaFuncSetAttribute(gemm_bf16x3<HDIM, false, false>, cudaFuncAttributeMaxDynamicSharedMemorySize, DSMEM_SZ);

    // 1) corruption + input split-pack
    corrupt_kernel<<<BROWS, 256>>>(x, u, r, low, high, qptr, 307, xp, xcp);

    // 2) weight fragment-packing (tiny)
    pack_w_kernel<<<(MDIM / 2 * HDIM) / 256, 256>>>(We0, w0hi, w0lo, MDIM);
    for (int i = 0; i < 5; i++)
        pack_w_kernel<<<(HDIM / 2 * HDIM) / 256, 256>>>(W65[i], whi(i), wlo(i), HDIM);

    // 3) 6 layers, bf16 split-3 tensor cores, both branches stacked
    dim3 grid(HDIM / 128, TOTROWS / 128);   // (2, 512)
    dim3 blk(256);

    gemm_bf16x3<MDIM, true,  true ><<<grid, blk, DSMEM_SZ>>>(xp, xcp, BROWS, w0hi, w0lo, bl[0], a0);
    gemm_bf16x3<HDIM, true,  true ><<<grid, blk, DSMEM_SZ>>>(a0, (const uint32_t*)0, TOTROWS, whi(0), wlo(0), bl[1], a1);
    gemm_bf16x3<HDIM, true,  true ><<<grid, blk, DSMEM_SZ>>>(a1, (const uint32_t*)0, TOTROWS, whi(1), wlo(1), bl[2], a0);
    gemm_bf16x3<HDIM, false, true ><<<grid, blk, DSMEM_SZ>>>(a0, (const uint32_t*)0, TOTROWS, whi(2), wlo(2), bl[3], a1);
    gemm_bf16x3<HDIM, true,  true ><<<grid, blk, DSMEM_SZ>>>(a1, (const uint32_t*)0, TOTROWS, whi(3), wlo(3), bl[4], a0);
    gemm_bf16x3<HDIM, false, false><<<grid, blk, DSMEM_SZ>>>(a0, (const uint32_t*)0, TOTROWS, whi(4), wlo(4), bl[5], out);

    (void)out_size;
}